// round 5
// baseline (speedup 1.0000x reference)
#include <cuda_runtime.h>
#include <cstdint>
#include <math_constants.h>

// Problem constants
#define NQ 8192
#define DD 256

// ---------------- scratch (no cudaMalloc allowed) ----------------
__device__ float g_Q[NQ * DD];
__device__ float g_K[NQ * DD];

// ---------------- f32x2 packed helpers (Blackwell FFMA2) ----------------
__device__ __forceinline__ uint64_t fma2(uint64_t a, uint64_t b, uint64_t c) {
    uint64_t d;
    asm("fma.rn.f32x2 %0, %1, %2, %3;" : "=l"(d) : "l"(a), "l"(b), "l"(c));
    return d;
}
__device__ __forceinline__ uint64_t mul2(uint64_t a, uint64_t b) {
    uint64_t d;
    asm("mul.rn.f32x2 %0, %1, %2;" : "=l"(d) : "l"(a), "l"(b));
    return d;
}
__device__ __forceinline__ uint64_t dup2(float f) {
    uint64_t r;
    asm("mov.b64 %0, {%1, %1};" : "=l"(r) : "f"(f));
    return r;
}
__device__ __forceinline__ float2 unp2(uint64_t v) {
    float2 f;
    asm("mov.b64 {%0, %1}, %2;" : "=f"(f.x), "=f"(f.y) : "l"(v));
    return f;
}

// ---------------- cp.async helpers ----------------
__device__ __forceinline__ void cp_async16(uint32_t saddr, const void* gaddr) {
    asm volatile("cp.async.cg.shared.global [%0], [%1], 16;" ::"r"(saddr), "l"(gaddr));
}
#define CP_COMMIT() asm volatile("cp.async.commit_group;" ::: "memory")
#define CP_WAIT0()  asm volatile("cp.async.wait_group 0;" ::: "memory")

// ---------------- Kernel 1: Q = X @ R, K = X @ E ----------------
__global__ __launch_bounds__(256) void qk_gemm(const float* __restrict__ X,
                                               const float* __restrict__ R,
                                               const float* __restrict__ E) {
    const float* W = blockIdx.z ? E : R;
    float* C = blockIdx.z ? g_K : g_Q;

    __shared__ float As[16][64];  // X^T tile: As[k][m]
    __shared__ float Bs[16][64];  // W tile:   Bs[k][n]

    const int t  = threadIdx.x;
    const int tx = t & 15;
    const int ty = t >> 4;
    const int m0 = blockIdx.x * 64;
    const int n0 = blockIdx.y * 64;

    float acc[4][4];
#pragma unroll
    for (int i = 0; i < 4; i++)
#pragma unroll
        for (int j = 0; j < 4; j++) acc[i][j] = 0.f;

    for (int k0 = 0; k0 < DD; k0 += 16) {
        {
            int row = t >> 2, kk = (t & 3) * 4;
            float4 v = *(const float4*)&X[(m0 + row) * DD + k0 + kk];
            As[kk + 0][row] = v.x;
            As[kk + 1][row] = v.y;
            As[kk + 2][row] = v.z;
            As[kk + 3][row] = v.w;
            int krow = t >> 4, col = (t & 15) * 4;
            *(float4*)&Bs[krow][col] = *(const float4*)&W[(k0 + krow) * DD + n0 + col];
        }
        __syncthreads();
#pragma unroll
        for (int kk = 0; kk < 16; kk++) {
            float a[4], b[4];
            *(float4*)a = *(const float4*)&As[kk][ty * 4];
            *(float4*)b = *(const float4*)&Bs[kk][tx * 4];
#pragma unroll
            for (int i = 0; i < 4; i++)
#pragma unroll
                for (int j = 0; j < 4; j++) acc[i][j] = fmaf(a[i], b[j], acc[i][j]);
        }
        __syncthreads();
    }
#pragma unroll
    for (int i = 0; i < 4; i++) {
        float4 v = make_float4(acc[i][0], acc[i][1], acc[i][2], acc[i][3]);
        *(float4*)&C[(m0 + ty * 4 + i) * DD + n0 + tx * 4] = v;
    }
}

// ---------------- Kernel 2: flash attention (fp32, f32x2, async K pipeline) ----
// Block: 256 threads (8 warps). BM=64 query rows (8/warp), BN=128 key chunk.
// K is streamed in 4 depth-slices of 64 per chunk, double-buffered via cp.async.
// Lane owns 4 K-columns {lane, lane+32, lane+64, lane+96} in the S-phase and
// 8 output d-columns {4*lane..+3, 128+4*lane..+3} in PV.
// smem: Qs[64][256] (64KB) + KB[2][128][68] (69.6KB) + Ps[64][128] (32KB) = 166KB
#define BM 64
#define BN 128
#define SLICE 64
#define NSL 4
#define KPITCH 68
#define RPW 8
#define NC 4
#define SKIP_THRESH 30.0f
#define NSTEPS ((NQ / BN) * NSL)  // 256

__global__ __launch_bounds__(256) void attn_kernel(const float* __restrict__ Xg,
                                                   float* __restrict__ Out) {
    extern __shared__ float sm[];
    float* Qs = sm;                          // BM*DD
    float* KB = Qs + BM * DD;                // 2 * BN * KPITCH
    float* Ps = KB + 2 * BN * KPITCH;        // BM*BN

    const int tid  = threadIdx.x;
    const int w    = tid >> 5;
    const int lane = tid & 31;
    const int q0   = blockIdx.x * BM;
    const int wr   = w * RPW;

    // fold 1/sqrt(d) and log2(e) into Q so softmax uses exp2
    const float qscale = 1.4426950408889634f / 16.0f;

    // load Q tile (scaled); visibility covered by the first pipeline barrier
    for (int i = tid; i < BM * DD / 4; i += 256) {
        float4 v = *(const float4*)&g_Q[(size_t)q0 * DD + i * 4];
        v.x *= qscale; v.y *= qscale; v.z *= qscale; v.w *= qscale;
        *(float4*)&Qs[i * 4] = v;
    }

    uint64_t o[RPW][4];
    float m[RPW], l[RPW];
#pragma unroll
    for (int r = 0; r < RPW; r++) {
        o[r][0] = o[r][1] = o[r][2] = o[r][3] = 0ull;
        m[r] = -CUDART_INF_F;
        l[r] = 0.f;
    }

    const float* qb = Qs + wr * DD;
    const uint32_t kb_smem = (uint32_t)__cvta_generic_to_shared(KB);

    // issue a depth-slice load: step st covers chunk (st>>2), slice (st&3)
    auto issue_load = [&](int st) {
        const int chunk = st >> 2, sl = st & 3;
        const float* src = g_K + (size_t)(chunk * BN) * DD + sl * SLICE;
        const uint32_t dst = kb_smem + (uint32_t)(st & 1) * (BN * KPITCH * 4);
#pragma unroll
        for (int ii = 0; ii < 8; ii++) {
            int i   = tid + ii * 256;
            int row = i >> 4, c4 = i & 15;
            cp_async16(dst + (row * KPITCH + c4 * 4) * 4,
                       src + (size_t)row * DD + c4 * 4);
        }
    };

    // prologue: start slice 0 of chunk 0
    issue_load(0);
    CP_COMMIT();

    int step = 0;
    for (int chunk = 0; chunk < NQ / BN; chunk++) {
        const int kb = chunk * BN;

        uint64_t sacc[RPW][NC];
#pragma unroll
        for (int r = 0; r < RPW; r++)
#pragma unroll
            for (int c = 0; c < NC; c++) sacc[r][c] = 0ull;

        // ---- S accumulation over 4 pipelined depth-slices ----
        for (int sl = 0; sl < NSL; sl++) {
            CP_WAIT0();        // this thread's portion of buf[step&1] arrived
            __syncthreads();   // publish to block; licenses overwrite of other buf
            if (step + 1 < NSTEPS) {
                issue_load(step + 1);
                CP_COMMIT();
            }

            const float* kbuf = KB + (step & 1) * (BN * KPITCH) + lane * KPITCH;
            const float* qs   = qb + sl * SLICE;
#pragma unroll 2
            for (int k = 0; k < SLICE; k += 4) {
                ulonglong2 kv[NC];
#pragma unroll
                for (int c = 0; c < NC; c++)
                    kv[c] = *(const ulonglong2*)(kbuf + c * 32 * KPITCH + k);
#pragma unroll
                for (int r = 0; r < RPW; r++) {
                    ulonglong2 q = *(const ulonglong2*)(qs + r * DD + k);
#pragma unroll
                    for (int c = 0; c < NC; c++) {
                        sacc[r][c] = fma2(q.x, kv[c].x, sacc[r][c]);
                        sacc[r][c] = fma2(q.y, kv[c].y, sacc[r][c]);
                    }
                }
            }
            step++;
        }

        // ---- reduce pairs, row max across warp, activity test ----
        float s[RPW][NC], rmax[RPW];
        bool act[RPW];
        int actmask = 0;
#pragma unroll
        for (int r = 0; r < RPW; r++) {
            float mx = -CUDART_INF_F;
#pragma unroll
            for (int c = 0; c < NC; c++) {
                float2 a = unp2(sacc[r][c]);
                s[r][c] = a.x + a.y;
                mx = fmaxf(mx, s[r][c]);
            }
#pragma unroll
            for (int off = 16; off > 0; off >>= 1)
                mx = fmaxf(mx, __shfl_xor_sync(0xffffffffu, mx, off));
            rmax[r] = mx;
            act[r] = (mx >= m[r] - SKIP_THRESH);  // warp-uniform
            if (act[r]) actmask |= (1 << r);
        }

        // ---- softmax update + Ps write for active rows (warp-private) ----
#pragma unroll
        for (int r = 0; r < RPW; r++) {
            if (act[r]) {
                float mnew  = fmaxf(m[r], rmax[r]);
                float alpha = exp2f(m[r] - mnew);
                float rs = 0.f;
                float p[NC];
#pragma unroll
                for (int c = 0; c < NC; c++) {
                    p[c] = exp2f(s[r][c] - mnew);
                    rs += p[c];
                }
#pragma unroll
                for (int off = 16; off > 0; off >>= 1)
                    rs += __shfl_xor_sync(0xffffffffu, rs, off);
                l[r] = l[r] * alpha + rs;
                m[r] = mnew;
                uint64_t a2 = dup2(alpha);
                o[r][0] = mul2(o[r][0], a2);
                o[r][1] = mul2(o[r][1], a2);
                o[r][2] = mul2(o[r][2], a2);
                o[r][3] = mul2(o[r][3], a2);
#pragma unroll
                for (int c = 0; c < NC; c++)
                    Ps[(wr + r) * BN + c * 32 + lane] = p[c];
            }
        }

        // ---- PV: jj-outer (X loads amortize across active rows) ----
        if (actmask) {
            __syncwarp();  // Ps visibility within warp
            const float* xb = Xg + (size_t)kb * DD + 4 * lane;
#pragma unroll 1
            for (int jj = 0; jj < BN; jj += 4) {
                ulonglong2 xv0[4], xv1[4];
#pragma unroll
                for (int ss = 0; ss < 4; ss++) {
                    const float* xc = xb + (jj + ss) * DD;
                    xv0[ss] = *(const ulonglong2*)(xc);
                    xv1[ss] = *(const ulonglong2*)(xc + 128);
                }
#pragma unroll
                for (int r = 0; r < RPW; r++) {
                    if (act[r]) {
                        float4 pv = *(const float4*)&Ps[(wr + r) * BN + jj];
                        uint64_t p0 = dup2(pv.x), p1 = dup2(pv.y);
                        uint64_t p2 = dup2(pv.z), p3 = dup2(pv.w);
                        o[r][0] = fma2(p0, xv0[0].x, o[r][0]);
                        o[r][1] = fma2(p0, xv0[0].y, o[r][1]);
                        o[r][2] = fma2(p0, xv1[0].x, o[r][2]);
                        o[r][3] = fma2(p0, xv1[0].y, o[r][3]);
                        o[r][0] = fma2(p1, xv0[1].x, o[r][0]);
                        o[r][1] = fma2(p1, xv0[1].y, o[r][1]);
                        o[r][2] = fma2(p1, xv1[1].x, o[r][2]);
                        o[r][3] = fma2(p1, xv1[1].y, o[r][3]);
                        o[r][0] = fma2(p2, xv0[2].x, o[r][0]);
                        o[r][1] = fma2(p2, xv0[2].y, o[r][1]);
                        o[r][2] = fma2(p2, xv1[2].x, o[r][2]);
                        o[r][3] = fma2(p2, xv1[2].y, o[r][3]);
                        o[r][0] = fma2(p3, xv0[3].x, o[r][0]);
                        o[r][1] = fma2(p3, xv0[3].y, o[r][1]);
                        o[r][2] = fma2(p3, xv1[3].x, o[r][2]);
                        o[r][3] = fma2(p3, xv1[3].y, o[r][3]);
                    }
                }
            }
        }
        // next chunk's first pipeline barrier separates PV from K-buffer reuse
    }

    // ---- epilogue: normalize and store ----
#pragma unroll
    for (int r = 0; r < RPW; r++) {
        float inv = 1.0f / l[r];
        int row = q0 + wr + r;
        float2 a = unp2(o[r][0]), b = unp2(o[r][1]);
        float2 c = unp2(o[r][2]), d = unp2(o[r][3]);
        float4 v0 = make_float4(a.x * inv, a.y * inv, b.x * inv, b.y * inv);
        float4 v1 = make_float4(c.x * inv, c.y * inv, d.x * inv, d.y * inv);
        *(float4*)&Out[(size_t)row * DD + 4 * lane]       = v0;
        *(float4*)&Out[(size_t)row * DD + 128 + 4 * lane] = v1;
    }
}

// ---------------- launch ----------------
extern "C" void kernel_launch(void* const* d_in, const int* in_sizes, int n_in,
                              void* d_out, int out_size) {
    const float* R = (const float*)d_in[0];  // rotation_params [256,256]
    const float* E = (const float*)d_in[1];  // entangle_params [256,256]
    const float* X = (const float*)d_in[2];  // inputs [8192,256]
    float* Out = (float*)d_out;

    const int smem_bytes = (BM * DD + 2 * BN * KPITCH + BM * BN) * 4;  // 167936 B
    cudaFuncSetAttribute(attn_kernel, cudaFuncAttributeMaxDynamicSharedMemorySize,
                         smem_bytes);

    qk_gemm<<<dim3(NQ / 64, DD / 64, 2), 256>>>(X, R, E);
    attn_kernel<<<NQ / BM, 256, smem_bytes>>>(X, Out);
}